// round 12
// baseline (speedup 1.0000x reference)
#include <cuda_runtime.h>
#include <cuda_fp16.h>
#include <mma.h>
#include <math.h>

using namespace nvcuda;

#define Nn      100000
#define F_IN    128
#define Hh      2
#define Cc      32
#define HC      64
#define Ee      3200000
#define Gg      64
#define EP      (Ee + Nn)       // 3,300,000 (divisible by 8)
#define NEG_SLOPE 0.2f
#define BCAP    96              // bucket capacity (Poisson(33): max cnt ~70, <<96)
#define NSLOT   (Nn * BCAP)     // 9,600,000

// ---------------- device scratch (static, no allocation) ----------------
__device__ __half  g_hw_h[Nn * HC];    // h = feat @ W^T (fp16, per layer)
__device__ __half  g_feat_h[Nn * HC];  // layer output after bias+elu (fp16)
__device__ float   g_as[Nn * Hh];
__device__ float   g_ad[Nn * Hh];
__device__ int     g_cnt[Nn];
__device__ int     g_esrc[NSLOT];      // bucketed src lists (.bss zero: pad slots -> node 0)
__device__ float2  g_ew[NSLOT];        // per-(edge,head) softmax weights (.bss zero pads)
__device__ float   g_pooled[Gg * HC];
__device__ __half  g_Wh[F_IN * HC + 2 * HC * HC];   // 16384: W hi parts, layers packed
__device__ __half  g_Wl[F_IN * HC + 2 * HC * HC];   // W lo (residual) parts

__device__ __forceinline__ float leaky(float x) { return fmaxf(x, NEG_SLOPE * x); }

// ---------------- one-time W hi/lo split ----------------
__global__ void wsplit_kernel(const float* __restrict__ W0,
                              const float* __restrict__ W1,
                              const float* __restrict__ W2)
{
    int i = blockIdx.x * 256 + threadIdx.x;      // 0..16383
    const float* src; int off;
    if (i < 8192)       { src = W0; off = 0; }
    else if (i < 12288) { src = W1; off = 8192; }
    else                { src = W2; off = 12288; }
    float f = src[i - off];
    __half h = __float2half_rn(f);
    g_Wh[i] = h;
    g_Wl[i] = __float2half_rn(f - __half2float(h));
}

// ---------------- adjacency build ----------------
__global__ void zero_cnt_kernel() {
    int i = blockIdx.x * blockDim.x + threadIdx.x;
    if (i < Nn) g_cnt[i] = 0;
}

// 8 edges per thread (round-10 config)
__global__ void scatter_kernel(const int* __restrict__ ei) {
    int e8 = (blockIdx.x * blockDim.x + threadIdx.x) * 8;
    if (e8 >= EP) return;
    if (e8 < Ee) {
        int4 s0 = *(const int4*)(ei + e8);
        int4 s1 = *(const int4*)(ei + e8 + 4);
        int4 d0 = *(const int4*)(ei + Ee + e8);
        int4 d1 = *(const int4*)(ei + Ee + e8 + 4);
        int p0 = atomicAdd(&g_cnt[d0.x], 1);
        int p1 = atomicAdd(&g_cnt[d0.y], 1);
        int p2 = atomicAdd(&g_cnt[d0.z], 1);
        int p3 = atomicAdd(&g_cnt[d0.w], 1);
        int p4 = atomicAdd(&g_cnt[d1.x], 1);
        int p5 = atomicAdd(&g_cnt[d1.y], 1);
        int p6 = atomicAdd(&g_cnt[d1.z], 1);
        int p7 = atomicAdd(&g_cnt[d1.w], 1);
        g_esrc[d0.x * BCAP + p0] = s0.x;
        g_esrc[d0.y * BCAP + p1] = s0.y;
        g_esrc[d0.z * BCAP + p2] = s0.z;
        g_esrc[d0.w * BCAP + p3] = s0.w;
        g_esrc[d1.x * BCAP + p4] = s1.x;
        g_esrc[d1.y * BCAP + p5] = s1.y;
        g_esrc[d1.z * BCAP + p6] = s1.z;
        g_esrc[d1.w * BCAP + p7] = s1.w;
    } else {
        int n = e8 - Ee;
        #pragma unroll
        for (int i = 0; i < 8; i++) {
            int pos = atomicAdd(&g_cnt[n + i], 1);
            g_esrc[(n + i) * BCAP + pos] = n + i;
        }
    }
}

// ---------------- split-precision WMMA GEMM + fused alpha epilogue ----------------
#define LDC 68

template<int K>
__global__ __launch_bounds__(256) void gemm_wmma_kernel(
    const float* __restrict__ A_in, int woff,
    const float* __restrict__ a_src, const float* __restrict__ a_dst)
{
    constexpr bool SPLIT_A = (K == F_IN);
    constexpr int KC = SPLIT_A ? 32 : 64;
    constexpr int LD = SPLIT_A ? 40 : 72;
    constexpr int O_AL = 128 * LD;
    constexpr int O_BH = SPLIT_A ? 2 * 128 * LD : 128 * LD;
    constexpr int O_BL = O_BH + 64 * LD;
    constexpr int STAGE_B = (O_BL + 64 * LD) * 2;
    constexpr int C_B = 128 * LDC * 4;
    constexpr int SMEM_B = (STAGE_B > C_B) ? STAGE_B : C_B;

    __shared__ __align__(128) char smem[SMEM_B];
    __half* sH = (__half*)smem;
    float*  sC = (float*)smem;

    int tid = threadIdx.x;
    int wid = tid >> 5;
    int row0 = blockIdx.x * 128;

    int r  = tid >> 1;
    int hf = tid & 1;
    int cbase = hf * 32;

    wmma::fragment<wmma::accumulator, 16, 16, 16, float> acc[4];
    #pragma unroll
    for (int n = 0; n < 4; n++) wmma::fill_fragment(acc[n], 0.f);

    #pragma unroll
    for (int k0 = 0; k0 < K; k0 += KC) {
        // ---- stage A ----
        {
            int grow = row0 + r;
            if (SPLIT_A) {
                int ks = hf * 16;
                #pragma unroll
                for (int i = 0; i < 4; i++) {
                    float4 v = (grow < Nn) ? *(const float4*)(A_in + grow * K + k0 + ks + i * 4)
                                           : make_float4(0.f, 0.f, 0.f, 0.f);
                    float f[4] = { v.x, v.y, v.z, v.w };
                    #pragma unroll
                    for (int j = 0; j < 4; j++) {
                        __half h = __float2half_rn(f[j]);
                        __half l = __float2half_rn(f[j] - __half2float(h));
                        sH[r * LD + ks + i * 4 + j]        = h;
                        sH[O_AL + r * LD + ks + i * 4 + j] = l;
                    }
                }
            } else {
                int ks = hf * 32;
                uint4 t0, t1, t2, t3;
                if (grow < Nn) {
                    const uint4* src = (const uint4*)(g_feat_h + grow * HC + k0 + ks);
                    t0 = src[0]; t1 = src[1]; t2 = src[2]; t3 = src[3];
                } else {
                    t0 = t1 = t2 = t3 = make_uint4(0, 0, 0, 0);
                }
                uint4* dst = (uint4*)(sH + r * LD + ks);
                dst[0] = t0; dst[1] = t1; dst[2] = t2; dst[3] = t3;
            }
        }
        // ---- stage B (precomputed hi/lo, plain fp16 copies) ----
        {
            int n  = tid >> 2;
            constexpr int NH = SPLIT_A ? 8 : 16;        // halves per thread
            int ks = (tid & 3) * NH;
            const __half* wh = g_Wh + woff + n * K + k0 + ks;
            const __half* wl = g_Wl + woff + n * K + k0 + ks;
            #pragma unroll
            for (int i = 0; i < NH / 8; i++) {
                *(uint4*)(sH + O_BH + n * LD + ks + i * 8) = *(const uint4*)(wh + i * 8);
                *(uint4*)(sH + O_BL + n * LD + ks + i * 8) = *(const uint4*)(wl + i * 8);
            }
        }
        __syncthreads();

        #pragma unroll
        for (int kk = 0; kk < KC; kk += 16) {
            wmma::fragment<wmma::matrix_a, 16, 16, 16, __half, wmma::row_major> a_h, a_l;
            wmma::load_matrix_sync(a_h, sH + (wid * 16) * LD + kk, LD);
            if (SPLIT_A)
                wmma::load_matrix_sync(a_l, sH + O_AL + (wid * 16) * LD + kk, LD);
            #pragma unroll
            for (int n = 0; n < 4; n++) {
                wmma::fragment<wmma::matrix_b, 16, 16, 16, __half, wmma::col_major> b_h, b_l;
                wmma::load_matrix_sync(b_h, sH + O_BH + (n * 16) * LD + kk, LD);
                wmma::load_matrix_sync(b_l, sH + O_BL + (n * 16) * LD + kk, LD);
                wmma::mma_sync(acc[n], a_h, b_h, acc[n]);
                wmma::mma_sync(acc[n], a_h, b_l, acc[n]);
                if (SPLIT_A)
                    wmma::mma_sync(acc[n], a_l, b_h, acc[n]);
            }
        }
        __syncthreads();
    }

    #pragma unroll
    for (int n = 0; n < 4; n++)
        wmma::store_matrix_sync(sC + (wid * 16) * LDC + n * 16, acc[n], LDC, wmma::mem_row_major);
    __syncthreads();

    int grow = row0 + r;
    if (grow < Nn) {
        const float* cp = sC + r * LDC + cbase;
        float ps = 0.f, pd = 0.f;
        __half2 outv[16];
        #pragma unroll
        for (int i = 0; i < 16; i++) {
            float2 v   = *(const float2*)(cp + 2 * i);
            float2 sa2 = *(const float2*)(a_src + cbase + 2 * i);
            float2 da2 = *(const float2*)(a_dst + cbase + 2 * i);
            ps += v.x * sa2.x + v.y * sa2.y;
            pd += v.x * da2.x + v.y * da2.y;
            outv[i] = __floats2half2_rn(v.x, v.y);
        }
        uint4* dst = (uint4*)(g_hw_h + grow * HC + cbase);
        const uint4* src = (const uint4*)outv;
        dst[0] = src[0]; dst[1] = src[1]; dst[2] = src[2]; dst[3] = src[3];
        g_as[grow * 2 + hf] = ps;
        g_ad[grow * 2 + hf] = pd;
    }
}

// ---------------- per-(edge,head) softmax weights ----------------
// Pure gather kernel, massive MLP; pads (slot >= cnt) never written -> stay 0.
__global__ __launch_bounds__(256) void edge_weight_kernel()
{
    int base = blockIdx.x * 1024 + threadIdx.x;
    #pragma unroll
    for (int i = 0; i < 4; i++) {
        int slot = base + i * 256;               // grid sized: 4*256*grid == NSLOT
        int d = slot / BCAP;
        int rr = slot - d * BCAP;
        if (rr < g_cnt[d]) {
            int s = g_esrc[slot];
            float2 asv = *(const float2*)(g_as + s * 2);
            float2 adv = *(const float2*)(g_ad + d * 2);
            float w0 = __expf(leaky(asv.x + adv.x));
            float w1 = __expf(leaky(asv.y + adv.y));
            g_ew[slot] = make_float2(w0, w1);
        }
    }
}

// ---------------- aggregation: one warp per destination node ----------------
// Predicate-free: pad slots have esrc=0 (valid row) and ew=0 -> contribute nothing.
__global__ __launch_bounds__(256) void aggregate_kernel(const float* __restrict__ bias)
{
    int wid  = (blockIdx.x * blockDim.x + threadIdx.x) >> 5;
    int lane = threadIdx.x & 31;
    if (wid >= Nn) return;
    int d  = wid;
    int lo = d * BCAP;
    int hi = lo + g_cnt[d];

    int e    = lane >> 2;        // edge within group of 8
    int r    = lane & 3;         // channel quarter
    int c    = r * 16;
    int head = r >> 1;

    unsigned long long acc[8];
    #pragma unroll
    for (int i = 0; i < 8; i++) acc[i] = 0ull;
    float wsum = 0.f;

    #pragma unroll 2
    for (int base = lo; base < hi; base += 8) {
        int k = base + e;
        int s = g_esrc[k];
        float2 wv = g_ew[k];
        float w = head ? wv.y : wv.x;
        unsigned long long w2;
        asm("mov.b64 %0, {%1,%2};" : "=l"(w2) : "f"(w), "f"(w));

        float v[8];
        const __half* hp = g_hw_h + s * HC + c;
        asm("ld.global.nc.v8.f32 {%0,%1,%2,%3,%4,%5,%6,%7}, [%8];"
            : "=f"(v[0]), "=f"(v[1]), "=f"(v[2]), "=f"(v[3]),
              "=f"(v[4]), "=f"(v[5]), "=f"(v[6]), "=f"(v[7])
            : "l"(hp));

        #pragma unroll
        for (int i = 0; i < 8; i++) {
            unsigned u = __float_as_uint(v[i]);
            float2 f = __half22float2(*(const __half2*)&u);
            unsigned long long fv;
            asm("mov.b64 %0, {%1,%2};" : "=l"(fv) : "f"(f.x), "f"(f.y));
            asm("fma.rn.f32x2 %0, %1, %2, %0;" : "+l"(acc[i]) : "l"(fv), "l"(w2));
        }
        wsum += w;
    }

    float a[16];
    #pragma unroll
    for (int i = 0; i < 8; i++)
        asm("mov.b64 {%0,%1}, %2;" : "=f"(a[2 * i]), "=f"(a[2 * i + 1]) : "l"(acc[i]));

    #pragma unroll
    for (int off = 4; off <= 16; off <<= 1) {
        #pragma unroll
        for (int i = 0; i < 16; i++)
            a[i] += __shfl_xor_sync(0xFFFFFFFFu, a[i], off);
        wsum += __shfl_xor_sync(0xFFFFFFFFu, wsum, off);
    }

    float inv = 1.f / (wsum + 1e-16f);
    int sub = (lane >> 2) * 2;
    int ch  = c + sub;
    float2 bv = *(const float2*)(bias + ch);
    float t0 = fmaf(a[sub],     inv, bv.x);
    float t1 = fmaf(a[sub + 1], inv, bv.y);
    t0 = (t0 > 0.f) ? t0 : (__expf(t0) - 1.f);
    t1 = (t1 > 0.f) ? t1 : (__expf(t1) - 1.f);
    *(__half2*)(g_feat_h + d * HC + ch) = __floats2half2_rn(t0, t1);
}

// ---------------- pooling ----------------
__device__ int lbound32(const int* arr, int n, int key) {
    int lo = 0, hi = n;
    while (lo < hi) {
        int mid = (lo + hi) >> 1;
        if (arr[mid] < key) lo = mid + 1; else hi = mid;
    }
    return lo;
}

__global__ void pool_kernel(const int* __restrict__ batch)
{
    int g = blockIdx.x;
    __shared__ int s_lo, s_hi;
    if (threadIdx.x == 0) {
        s_lo = lbound32(batch, Nn, g);
        s_hi = lbound32(batch, Nn, g + 1);
    }
    __syncthreads();
    int lo = s_lo, hi = s_hi;
    int lane = threadIdx.x & 63;
    int sub  = threadIdx.x >> 6;
    float acc = 0.f;
    for (int n = lo + sub; n < hi; n += 4)
        acc += __half2float(g_feat_h[n * HC + lane]);
    __shared__ float red[4][64];
    red[sub][lane] = acc;
    __syncthreads();
    if (sub == 0) {
        float v = red[0][lane] + red[1][lane] + red[2][lane] + red[3][lane];
        float cnt = (float)(hi - lo);
        v /= fmaxf(cnt, 1.0f);
        g_pooled[g * HC + lane] = v;
    }
}

// ---------------- MLP head ----------------
__global__ void mlp_kernel(const float* __restrict__ w1, const float* __restrict__ b1,
                           const float* __restrict__ w2, const float* __restrict__ b2,
                           float* __restrict__ out)
{
    __shared__ float sw1[Cc * HC];
    __shared__ float sw2[2 * Cc];
    int t = threadIdx.x;
    for (int i = t; i < Cc * HC; i += 64) sw1[i] = w1[i];
    if (t < 2 * Cc) sw2[t] = w2[t];
    __syncthreads();
    if (t >= Gg) return;
    float p[HC];
    #pragma unroll
    for (int i = 0; i < HC; i++) p[i] = g_pooled[t * HC + i];
    float o0 = b2[0], o1 = b2[1];
    #pragma unroll 4
    for (int jj = 0; jj < Cc; jj++) {
        float z = b1[jj];
        #pragma unroll
        for (int i = 0; i < HC; i++) z = fmaf(p[i], sw1[jj * HC + i], z);
        z = fmaxf(z, 0.f);
        o0 = fmaf(z, sw2[jj], o0);
        o1 = fmaf(z, sw2[Cc + jj], o1);
    }
    out[t * 2]     = o0;
    out[t * 2 + 1] = o1;
}

// ---------------- launch ----------------
extern "C" void kernel_launch(void* const* d_in, const int* in_sizes, int n_in,
                              void* d_out, int out_size)
{
    const float* x      = (const float*)d_in[0];
    const int*   ei     = (const int*)d_in[1];
    const int*   batch  = (const int*)d_in[2];
    const float* W[3]     = { (const float*)d_in[3],  (const float*)d_in[7],  (const float*)d_in[11] };
    const float* a_src[3] = { (const float*)d_in[4],  (const float*)d_in[8],  (const float*)d_in[12] };
    const float* a_dst[3] = { (const float*)d_in[5],  (const float*)d_in[9],  (const float*)d_in[13] };
    const float* b[3]     = { (const float*)d_in[6],  (const float*)d_in[10], (const float*)d_in[14] };
    const float* mlp_w1 = (const float*)d_in[15];
    const float* mlp_b1 = (const float*)d_in[16];
    const float* mlp_w2 = (const float*)d_in[17];
    const float* mlp_b2 = (const float*)d_in[18];
    float* out = (float*)d_out;

    wsplit_kernel<<<64, 256>>>(W[0], W[1], W[2]);
    zero_cnt_kernel<<<(Nn + 255) / 256, 256>>>();
    scatter_kernel<<<(EP / 8 + 255) / 256, 256>>>(ei);

    const int gemm_grid = (Nn + 127) / 128;
    const int woff[3] = { 0, F_IN * HC, F_IN * HC + HC * HC };
    for (int l = 0; l < 3; l++) {
        if (l == 0) gemm_wmma_kernel<F_IN><<<gemm_grid, 256>>>(x, woff[l], a_src[l], a_dst[l]);
        else        gemm_wmma_kernel<HC>  <<<gemm_grid, 256>>>(x, woff[l], a_src[l], a_dst[l]);
        edge_weight_kernel<<<NSLOT / 1024, 256>>>();
        aggregate_kernel<<<(Nn * 32 + 255) / 256, 256>>>(b[l]);
    }

    pool_kernel<<<Gg, 256>>>(batch);
    mlp_kernel<<<1, 64>>>(mlp_w1, mlp_b1, mlp_w2, mlp_b2, out);
}

// round 13
// speedup vs baseline: 1.1993x; 1.1993x over previous
#include <cuda_runtime.h>
#include <cuda_fp16.h>
#include <mma.h>
#include <math.h>

using namespace nvcuda;

#define Nn      100000
#define F_IN    128
#define Hh      2
#define Cc      32
#define HC      64
#define Ee      3200000
#define Gg      64
#define EP      (Ee + Nn)       // 3,300,000 (divisible by 8)
#define NEG_SLOPE 0.2f
#define BCAP    96              // bucket capacity (Poisson(33): P(>=95) ~ 0)

// ---------------- device scratch (static, no allocation) ----------------
__device__ __half  g_hw_h[Nn * HC];    // h = feat @ W^T (fp16, per layer)
__device__ __half  g_feat_h[Nn * HC];  // layer output after bias+elu (fp16)
__device__ float   g_as[Nn * Hh];
__device__ float   g_ad[Nn * Hh];
__device__ int     g_cnt[Nn];
__device__ int     g_esrc[Nn * BCAP];  // bucketed src lists
__device__ float   g_pooled[Gg * HC];
__device__ __half  g_Wh[F_IN * HC + 2 * HC * HC];   // W hi parts, layers packed
__device__ __half  g_Wl[F_IN * HC + 2 * HC * HC];   // W lo (residual) parts

__device__ __forceinline__ float leaky(float x) { return fmaxf(x, NEG_SLOPE * x); }

// ---------------- one-time W hi/lo split ----------------
__global__ void wsplit_kernel(const float* __restrict__ W0,
                              const float* __restrict__ W1,
                              const float* __restrict__ W2)
{
    int i = blockIdx.x * 256 + threadIdx.x;      // 0..16383
    const float* src; int off;
    if (i < 8192)       { src = W0; off = 0; }
    else if (i < 12288) { src = W1; off = 8192; }
    else                { src = W2; off = 12288; }
    float f = src[i - off];
    __half h = __float2half_rn(f);
    g_Wh[i] = h;
    g_Wl[i] = __float2half_rn(f - __half2float(h));
}

// ---------------- adjacency build ----------------
__global__ void zero_cnt_kernel() {
    int i = blockIdx.x * blockDim.x + threadIdx.x;
    if (i < Nn) g_cnt[i] = 0;
}

// 8 edges per thread (round-10 config)
__global__ void scatter_kernel(const int* __restrict__ ei) {
    int e8 = (blockIdx.x * blockDim.x + threadIdx.x) * 8;
    if (e8 >= EP) return;
    if (e8 < Ee) {
        int4 s0 = *(const int4*)(ei + e8);
        int4 s1 = *(const int4*)(ei + e8 + 4);
        int4 d0 = *(const int4*)(ei + Ee + e8);
        int4 d1 = *(const int4*)(ei + Ee + e8 + 4);
        int p0 = atomicAdd(&g_cnt[d0.x], 1);
        int p1 = atomicAdd(&g_cnt[d0.y], 1);
        int p2 = atomicAdd(&g_cnt[d0.z], 1);
        int p3 = atomicAdd(&g_cnt[d0.w], 1);
        int p4 = atomicAdd(&g_cnt[d1.x], 1);
        int p5 = atomicAdd(&g_cnt[d1.y], 1);
        int p6 = atomicAdd(&g_cnt[d1.z], 1);
        int p7 = atomicAdd(&g_cnt[d1.w], 1);
        g_esrc[d0.x * BCAP + p0] = s0.x;
        g_esrc[d0.y * BCAP + p1] = s0.y;
        g_esrc[d0.z * BCAP + p2] = s0.z;
        g_esrc[d0.w * BCAP + p3] = s0.w;
        g_esrc[d1.x * BCAP + p4] = s1.x;
        g_esrc[d1.y * BCAP + p5] = s1.y;
        g_esrc[d1.z * BCAP + p6] = s1.z;
        g_esrc[d1.w * BCAP + p7] = s1.w;
    } else {
        int n = e8 - Ee;
        #pragma unroll
        for (int i = 0; i < 8; i++) {
            int pos = atomicAdd(&g_cnt[n + i], 1);
            g_esrc[(n + i) * BCAP + pos] = n + i;
        }
    }
}

// ---------------- WMMA GEMM (W split hi+lo, A plain fp16) + fused alpha ----------------
// C[m,n] = sum_k A[m,k]*W[n,k] ~= A16*(Wh + Wl), fp32 accumulate.
// A-rounding noise is per-node random (same scale as fp16 g_hw storage noise);
// W-rounding would be systematic, hence the split.
#define LDC 68
#define LDH 72

template<int K>
__global__ __launch_bounds__(256) void gemm_wmma_kernel(
    const float* __restrict__ A_in, int woff,
    const float* __restrict__ a_src, const float* __restrict__ a_dst)
{
    constexpr int O_BH = 128 * LDH;             // halves
    constexpr int O_BL = O_BH + 64 * LDH;
    constexpr int STAGE_B = (O_BL + 64 * LDH) * 2;   // 36864B
    constexpr int C_B = 128 * LDC * 4;               // 34816B
    constexpr int SMEM_B = (STAGE_B > C_B) ? STAGE_B : C_B;

    __shared__ __align__(128) char smem[SMEM_B];
    __half* sH = (__half*)smem;
    float*  sC = (float*)smem;

    int tid = threadIdx.x;
    int wid = tid >> 5;
    int row0 = blockIdx.x * 128;

    int r  = tid >> 1;        // 0..127
    int hf = tid & 1;
    int cbase = hf * 32;

    wmma::fragment<wmma::accumulator, 16, 16, 16, float> acc[4];
    #pragma unroll
    for (int n = 0; n < 4; n++) wmma::fill_fragment(acc[n], 0.f);

    #pragma unroll
    for (int k0 = 0; k0 < K; k0 += 64) {
        // ---- stage A tile: 128 rows x 64 k, fp16 ----
        {
            int grow = row0 + r;
            int ks = hf * 32;                 // 32 halves per thread
            if (K == F_IN) {
                __half2 tmp[16];
                if (grow < Nn) {
                    #pragma unroll
                    for (int i = 0; i < 8; i++) {
                        float4 v = *(const float4*)(A_in + grow * K + k0 + ks + i * 4);
                        tmp[2*i]   = __floats2half2_rn(v.x, v.y);
                        tmp[2*i+1] = __floats2half2_rn(v.z, v.w);
                    }
                } else {
                    #pragma unroll
                    for (int i = 0; i < 16; i++) tmp[i] = __floats2half2_rn(0.f, 0.f);
                }
                uint4* dst = (uint4*)(sH + r * LDH + ks);
                const uint4* sp = (const uint4*)tmp;
                dst[0] = sp[0]; dst[1] = sp[1]; dst[2] = sp[2]; dst[3] = sp[3];
            } else {
                uint4 t0, t1, t2, t3;
                if (grow < Nn) {
                    const uint4* src = (const uint4*)(g_feat_h + grow * HC + k0 + ks);
                    t0 = src[0]; t1 = src[1]; t2 = src[2]; t3 = src[3];
                } else {
                    t0 = t1 = t2 = t3 = make_uint4(0, 0, 0, 0);
                }
                uint4* dst = (uint4*)(sH + r * LDH + ks);
                dst[0] = t0; dst[1] = t1; dst[2] = t2; dst[3] = t3;
            }
        }
        // ---- stage B tile: precomputed hi/lo, pure copies ----
        {
            int n  = tid >> 2;                 // 0..63
            int ks = (tid & 3) * 16;           // 16 halves per thread
            const __half* wh = g_Wh + woff + n * K + k0 + ks;
            const __half* wl = g_Wl + woff + n * K + k0 + ks;
            *(uint4*)(sH + O_BH + n * LDH + ks)     = *(const uint4*)(wh);
            *(uint4*)(sH + O_BH + n * LDH + ks + 8) = *(const uint4*)(wh + 8);
            *(uint4*)(sH + O_BL + n * LDH + ks)     = *(const uint4*)(wl);
            *(uint4*)(sH + O_BL + n * LDH + ks + 8) = *(const uint4*)(wl + 8);
        }
        __syncthreads();

        #pragma unroll
        for (int kk = 0; kk < 64; kk += 16) {
            wmma::fragment<wmma::matrix_a, 16, 16, 16, __half, wmma::row_major> a_h;
            wmma::load_matrix_sync(a_h, sH + (wid * 16) * LDH + kk, LDH);
            #pragma unroll
            for (int n = 0; n < 4; n++) {
                wmma::fragment<wmma::matrix_b, 16, 16, 16, __half, wmma::col_major> b_h, b_l;
                wmma::load_matrix_sync(b_h, sH + O_BH + (n * 16) * LDH + kk, LDH);
                wmma::load_matrix_sync(b_l, sH + O_BL + (n * 16) * LDH + kk, LDH);
                wmma::mma_sync(acc[n], a_h, b_h, acc[n]);
                wmma::mma_sync(acc[n], a_h, b_l, acc[n]);
            }
        }
        __syncthreads();
    }

    // ---- stage C to smem fp32 ----
    #pragma unroll
    for (int n = 0; n < 4; n++)
        wmma::store_matrix_sync(sC + (wid * 16) * LDC + n * 16, acc[n], LDC, wmma::mem_row_major);
    __syncthreads();

    // ---- epilogue: thread owns (row r, head hf) ----
    int grow = row0 + r;
    if (grow < Nn) {
        const float* cp = sC + r * LDC + cbase;
        float ps = 0.f, pd = 0.f;
        __half2 outv[16];
        #pragma unroll
        for (int i = 0; i < 16; i++) {
            float2 v   = *(const float2*)(cp + 2 * i);
            float2 sa2 = *(const float2*)(a_src + cbase + 2 * i);
            float2 da2 = *(const float2*)(a_dst + cbase + 2 * i);
            ps += v.x * sa2.x + v.y * sa2.y;
            pd += v.x * da2.x + v.y * da2.y;
            outv[i] = __floats2half2_rn(v.x, v.y);
        }
        uint4* dst = (uint4*)(g_hw_h + grow * HC + cbase);
        const uint4* src = (const uint4*)outv;
        dst[0] = src[0]; dst[1] = src[1]; dst[2] = src[2]; dst[3] = src[3];
        g_as[grow * 2 + hf] = ps;
        g_ad[grow * 2 + hf] = pd;
    }
}

// ---------------- aggregation: one warp per destination node (round-10 loop) ----------------
__global__ __launch_bounds__(256) void aggregate_kernel(const float* __restrict__ bias)
{
    int wid  = (blockIdx.x * blockDim.x + threadIdx.x) >> 5;
    int lane = threadIdx.x & 31;
    if (wid >= Nn) return;
    int d  = wid;
    int lo = d * BCAP;
    int hi = lo + g_cnt[d];

    int e    = lane >> 2;        // 0..7: edge within group of 8
    int r    = lane & 3;         // channel quarter
    int c    = r * 16;           // channel base
    int head = r >> 1;

    float adh = g_ad[d * 2 + head];

    unsigned long long acc[8];
    #pragma unroll
    for (int i = 0; i < 8; i++) acc[i] = 0ull;
    float wsum = 0.f;

    for (int base = lo; base < hi; base += 8) {
        int k = base + e;
        if (k < hi) {
            int s = g_esrc[k];
            float ev = leaky(g_as[s * 2 + head] + adh);
            float w = __expf(ev);
            unsigned long long w2;
            asm("mov.b64 %0, {%1,%2};" : "=l"(w2) : "f"(w), "f"(w));

            float v[8];
            const __half* hp = g_hw_h + s * HC + c;
            asm("ld.global.nc.v8.f32 {%0,%1,%2,%3,%4,%5,%6,%7}, [%8];"
                : "=f"(v[0]), "=f"(v[1]), "=f"(v[2]), "=f"(v[3]),
                  "=f"(v[4]), "=f"(v[5]), "=f"(v[6]), "=f"(v[7])
                : "l"(hp));

            #pragma unroll
            for (int i = 0; i < 8; i++) {
                unsigned u = __float_as_uint(v[i]);
                float2 f = __half22float2(*(const __half2*)&u);
                unsigned long long fv;
                asm("mov.b64 %0, {%1,%2};" : "=l"(fv) : "f"(f.x), "f"(f.y));
                asm("fma.rn.f32x2 %0, %1, %2, %0;" : "+l"(acc[i]) : "l"(fv), "l"(w2));
            }
            wsum += w;
        }
    }

    float a[16];
    #pragma unroll
    for (int i = 0; i < 8; i++)
        asm("mov.b64 {%0,%1}, %2;" : "=f"(a[2 * i]), "=f"(a[2 * i + 1]) : "l"(acc[i]));

    #pragma unroll
    for (int off = 4; off <= 16; off <<= 1) {
        #pragma unroll
        for (int i = 0; i < 16; i++)
            a[i] += __shfl_xor_sync(0xFFFFFFFFu, a[i], off);
        wsum += __shfl_xor_sync(0xFFFFFFFFu, wsum, off);
    }

    float inv = 1.f / (wsum + 1e-16f);
    int sub = (lane >> 2) * 2;
    int ch  = c + sub;
    float2 bv = *(const float2*)(bias + ch);
    float t0 = fmaf(a[sub],     inv, bv.x);
    float t1 = fmaf(a[sub + 1], inv, bv.y);
    t0 = (t0 > 0.f) ? t0 : (__expf(t0) - 1.f);
    t1 = (t1 > 0.f) ? t1 : (__expf(t1) - 1.f);
    *(__half2*)(g_feat_h + d * HC + ch) = __floats2half2_rn(t0, t1);
}

// ---------------- pooling ----------------
__device__ int lbound32(const int* arr, int n, int key) {
    int lo = 0, hi = n;
    while (lo < hi) {
        int mid = (lo + hi) >> 1;
        if (arr[mid] < key) lo = mid + 1; else hi = mid;
    }
    return lo;
}

__global__ void pool_kernel(const int* __restrict__ batch)
{
    int g = blockIdx.x;
    __shared__ int s_lo, s_hi;
    if (threadIdx.x == 0) {
        s_lo = lbound32(batch, Nn, g);
        s_hi = lbound32(batch, Nn, g + 1);
    }
    __syncthreads();
    int lo = s_lo, hi = s_hi;
    int lane = threadIdx.x & 63;
    int sub  = threadIdx.x >> 6;
    float acc = 0.f;
    for (int n = lo + sub; n < hi; n += 4)
        acc += __half2float(g_feat_h[n * HC + lane]);
    __shared__ float red[4][64];
    red[sub][lane] = acc;
    __syncthreads();
    if (sub == 0) {
        float v = red[0][lane] + red[1][lane] + red[2][lane] + red[3][lane];
        float cnt = (float)(hi - lo);
        v /= fmaxf(cnt, 1.0f);
        g_pooled[g * HC + lane] = v;
    }
}

// ---------------- MLP head ----------------
__global__ void mlp_kernel(const float* __restrict__ w1, const float* __restrict__ b1,
                           const float* __restrict__ w2, const float* __restrict__ b2,
                           float* __restrict__ out)
{
    __shared__ float sw1[Cc * HC];
    __shared__ float sw2[2 * Cc];
    int t = threadIdx.x;
    for (int i = t; i < Cc * HC; i += 64) sw1[i] = w1[i];
    if (t < 2 * Cc) sw2[t] = w2[t];
    __syncthreads();
    if (t >= Gg) return;
    float p[HC];
    #pragma unroll
    for (int i = 0; i < HC; i++) p[i] = g_pooled[t * HC + i];
    float o0 = b2[0], o1 = b2[1];
    #pragma unroll 4
    for (int jj = 0; jj < Cc; jj++) {
        float z = b1[jj];
        #pragma unroll
        for (int i = 0; i < HC; i++) z = fmaf(p[i], sw1[jj * HC + i], z);
        z = fmaxf(z, 0.f);
        o0 = fmaf(z, sw2[jj], o0);
        o1 = fmaf(z, sw2[Cc + jj], o1);
    }
    out[t * 2]     = o0;
    out[t * 2 + 1] = o1;
}

// ---------------- launch ----------------
extern "C" void kernel_launch(void* const* d_in, const int* in_sizes, int n_in,
                              void* d_out, int out_size)
{
    const float* x      = (const float*)d_in[0];
    const int*   ei     = (const int*)d_in[1];
    const int*   batch  = (const int*)d_in[2];
    const float* W[3]     = { (const float*)d_in[3],  (const float*)d_in[7],  (const float*)d_in[11] };
    const float* a_src[3] = { (const float*)d_in[4],  (const float*)d_in[8],  (const float*)d_in[12] };
    const float* a_dst[3] = { (const float*)d_in[5],  (const float*)d_in[9],  (const float*)d_in[13] };
    const float* b[3]     = { (const float*)d_in[6],  (const float*)d_in[10], (const float*)d_in[14] };
    const float* mlp_w1 = (const float*)d_in[15];
    const float* mlp_b1 = (const float*)d_in[16];
    const float* mlp_w2 = (const float*)d_in[17];
    const float* mlp_b2 = (const float*)d_in[18];
    float* out = (float*)d_out;

    wsplit_kernel<<<64, 256>>>(W[0], W[1], W[2]);
    zero_cnt_kernel<<<(Nn + 255) / 256, 256>>>();
    scatter_kernel<<<(EP / 8 + 255) / 256, 256>>>(ei);

    const int gemm_grid = (Nn + 127) / 128;
    const int woff[3] = { 0, F_IN * HC, F_IN * HC + HC * HC };
    for (int l = 0; l < 3; l++) {
        if (l == 0) gemm_wmma_kernel<F_IN><<<gemm_grid, 256>>>(x, woff[l], a_src[l], a_dst[l]);
        else        gemm_wmma_kernel<HC>  <<<gemm_grid, 256>>>(x, woff[l], a_src[l], a_dst[l]);
        aggregate_kernel<<<(Nn * 32 + 255) / 256, 256>>>(b[l]);
    }

    pool_kernel<<<Gg, 256>>>(batch);
    mlp_kernel<<<1, 64>>>(mlp_w1, mlp_b1, mlp_w2, mlp_b2, out);
}

// round 14
// speedup vs baseline: 1.2080x; 1.0072x over previous
#include <cuda_runtime.h>
#include <cuda_fp16.h>
#include <mma.h>
#include <math.h>

using namespace nvcuda;

#define Nn      100000
#define F_IN    128
#define Hh      2
#define Cc      32
#define HC      64
#define Ee      3200000
#define Gg      64
#define EP      (Ee + Nn)       // 3,300,000 (divisible by 8)
#define NEG_SLOPE 0.2f
#define BCAP    96              // bucket capacity (Poisson(33): P(>=95) ~ 0)

// ---------------- device scratch (static, no allocation) ----------------
__device__ __half  g_hw_h[Nn * HC];    // h = feat @ W^T (fp16, per layer)
__device__ __half  g_feat_h[Nn * HC];  // layer output after bias+elu (fp16)
__device__ float   g_as[Nn * Hh];
__device__ float   g_ad[Nn * Hh];
__device__ int     g_cnt[Nn];
__device__ int     g_esrc[Nn * BCAP];  // bucketed src lists
__device__ float   g_pooled[Gg * HC];
__device__ __half  g_Wh[F_IN * HC + 2 * HC * HC];   // W hi parts, layers packed
__device__ __half  g_Wl[F_IN * HC + 2 * HC * HC];   // W lo (residual) parts

__device__ __forceinline__ float leaky(float x) { return fmaxf(x, NEG_SLOPE * x); }

// ---------------- one-time W hi/lo split ----------------
__global__ void wsplit_kernel(const float* __restrict__ W0,
                              const float* __restrict__ W1,
                              const float* __restrict__ W2)
{
    int i = blockIdx.x * 256 + threadIdx.x;      // 0..16383
    const float* src; int off;
    if (i < 8192)       { src = W0; off = 0; }
    else if (i < 12288) { src = W1; off = 8192; }
    else                { src = W2; off = 12288; }
    float f = src[i - off];
    __half h = __float2half_rn(f);
    g_Wh[i] = h;
    g_Wl[i] = __float2half_rn(f - __half2float(h));
}

// ---------------- adjacency build ----------------
__global__ void zero_cnt_kernel() {
    int i = blockIdx.x * blockDim.x + threadIdx.x;
    if (i < Nn) g_cnt[i] = 0;
}

// 8 edges per thread (round-10 config)
__global__ void scatter_kernel(const int* __restrict__ ei) {
    int e8 = (blockIdx.x * blockDim.x + threadIdx.x) * 8;
    if (e8 >= EP) return;
    if (e8 < Ee) {
        int4 s0 = *(const int4*)(ei + e8);
        int4 s1 = *(const int4*)(ei + e8 + 4);
        int4 d0 = *(const int4*)(ei + Ee + e8);
        int4 d1 = *(const int4*)(ei + Ee + e8 + 4);
        int p0 = atomicAdd(&g_cnt[d0.x], 1);
        int p1 = atomicAdd(&g_cnt[d0.y], 1);
        int p2 = atomicAdd(&g_cnt[d0.z], 1);
        int p3 = atomicAdd(&g_cnt[d0.w], 1);
        int p4 = atomicAdd(&g_cnt[d1.x], 1);
        int p5 = atomicAdd(&g_cnt[d1.y], 1);
        int p6 = atomicAdd(&g_cnt[d1.z], 1);
        int p7 = atomicAdd(&g_cnt[d1.w], 1);
        g_esrc[d0.x * BCAP + p0] = s0.x;
        g_esrc[d0.y * BCAP + p1] = s0.y;
        g_esrc[d0.z * BCAP + p2] = s0.z;
        g_esrc[d0.w * BCAP + p3] = s0.w;
        g_esrc[d1.x * BCAP + p4] = s1.x;
        g_esrc[d1.y * BCAP + p5] = s1.y;
        g_esrc[d1.z * BCAP + p6] = s1.z;
        g_esrc[d1.w * BCAP + p7] = s1.w;
    } else {
        int n = e8 - Ee;
        #pragma unroll
        for (int i = 0; i < 8; i++) {
            int pos = atomicAdd(&g_cnt[n + i], 1);
            g_esrc[(n + i) * BCAP + pos] = n + i;
        }
    }
}

// ---------------- WMMA GEMM (W split hi+lo, A plain fp16) + fused alpha ----------------
// C[m,n] = sum_k A[m,k]*W[n,k] ~= A16*(Wh + Wl), fp32 accumulate.
// __launch_bounds__(256,4): cap regs at 64 -> 4 blocks/SM (was 3 @ regs=80).
#define LDC 68
#define LDH 72

template<int K>
__global__ __launch_bounds__(256, 4) void gemm_wmma_kernel(
    const float* __restrict__ A_in, int woff,
    const float* __restrict__ a_src, const float* __restrict__ a_dst)
{
    constexpr int O_BH = 128 * LDH;             // halves
    constexpr int O_BL = O_BH + 64 * LDH;
    constexpr int STAGE_B = (O_BL + 64 * LDH) * 2;   // 36864B
    constexpr int C_B = 128 * LDC * 4;               // 34816B
    constexpr int SMEM_B = (STAGE_B > C_B) ? STAGE_B : C_B;

    __shared__ __align__(128) char smem[SMEM_B];
    __half* sH = (__half*)smem;
    float*  sC = (float*)smem;

    int tid = threadIdx.x;
    int wid = tid >> 5;
    int row0 = blockIdx.x * 128;

    int r  = tid >> 1;        // 0..127
    int hf = tid & 1;
    int cbase = hf * 32;

    wmma::fragment<wmma::accumulator, 16, 16, 16, float> acc[4];
    #pragma unroll
    for (int n = 0; n < 4; n++) wmma::fill_fragment(acc[n], 0.f);

    #pragma unroll
    for (int k0 = 0; k0 < K; k0 += 64) {
        // ---- stage A tile: 128 rows x 64 k, fp16 ----
        {
            int grow = row0 + r;
            int ks = hf * 32;                 // 32 halves per thread
            if (K == F_IN) {
                __half2 tmp[16];
                if (grow < Nn) {
                    #pragma unroll
                    for (int i = 0; i < 8; i++) {
                        float4 v = *(const float4*)(A_in + grow * K + k0 + ks + i * 4);
                        tmp[2*i]   = __floats2half2_rn(v.x, v.y);
                        tmp[2*i+1] = __floats2half2_rn(v.z, v.w);
                    }
                } else {
                    #pragma unroll
                    for (int i = 0; i < 16; i++) tmp[i] = __floats2half2_rn(0.f, 0.f);
                }
                uint4* dst = (uint4*)(sH + r * LDH + ks);
                const uint4* sp = (const uint4*)tmp;
                dst[0] = sp[0]; dst[1] = sp[1]; dst[2] = sp[2]; dst[3] = sp[3];
            } else {
                uint4 t0, t1, t2, t3;
                if (grow < Nn) {
                    const uint4* src = (const uint4*)(g_feat_h + grow * HC + k0 + ks);
                    t0 = src[0]; t1 = src[1]; t2 = src[2]; t3 = src[3];
                } else {
                    t0 = t1 = t2 = t3 = make_uint4(0, 0, 0, 0);
                }
                uint4* dst = (uint4*)(sH + r * LDH + ks);
                dst[0] = t0; dst[1] = t1; dst[2] = t2; dst[3] = t3;
            }
        }
        // ---- stage B tile: precomputed hi/lo, pure copies ----
        {
            int n  = tid >> 2;                 // 0..63
            int ks = (tid & 3) * 16;           // 16 halves per thread
            const __half* wh = g_Wh + woff + n * K + k0 + ks;
            const __half* wl = g_Wl + woff + n * K + k0 + ks;
            *(uint4*)(sH + O_BH + n * LDH + ks)     = *(const uint4*)(wh);
            *(uint4*)(sH + O_BH + n * LDH + ks + 8) = *(const uint4*)(wh + 8);
            *(uint4*)(sH + O_BL + n * LDH + ks)     = *(const uint4*)(wl);
            *(uint4*)(sH + O_BL + n * LDH + ks + 8) = *(const uint4*)(wl + 8);
        }
        __syncthreads();

        #pragma unroll
        for (int kk = 0; kk < 64; kk += 16) {
            wmma::fragment<wmma::matrix_a, 16, 16, 16, __half, wmma::row_major> a_h;
            wmma::load_matrix_sync(a_h, sH + (wid * 16) * LDH + kk, LDH);
            #pragma unroll
            for (int n = 0; n < 4; n++) {
                wmma::fragment<wmma::matrix_b, 16, 16, 16, __half, wmma::col_major> b_h, b_l;
                wmma::load_matrix_sync(b_h, sH + O_BH + (n * 16) * LDH + kk, LDH);
                wmma::load_matrix_sync(b_l, sH + O_BL + (n * 16) * LDH + kk, LDH);
                wmma::mma_sync(acc[n], a_h, b_h, acc[n]);
                wmma::mma_sync(acc[n], a_h, b_l, acc[n]);
            }
        }
        __syncthreads();
    }

    // ---- stage C to smem fp32 ----
    #pragma unroll
    for (int n = 0; n < 4; n++)
        wmma::store_matrix_sync(sC + (wid * 16) * LDC + n * 16, acc[n], LDC, wmma::mem_row_major);
    __syncthreads();

    // ---- epilogue: thread owns (row r, head hf) ----
    int grow = row0 + r;
    if (grow < Nn) {
        const float* cp = sC + r * LDC + cbase;
        float ps = 0.f, pd = 0.f;
        __half2 outv[16];
        #pragma unroll
        for (int i = 0; i < 16; i++) {
            float2 v   = *(const float2*)(cp + 2 * i);
            float2 sa2 = *(const float2*)(a_src + cbase + 2 * i);
            float2 da2 = *(const float2*)(a_dst + cbase + 2 * i);
            ps += v.x * sa2.x + v.y * sa2.y;
            pd += v.x * da2.x + v.y * da2.y;
            outv[i] = __floats2half2_rn(v.x, v.y);
        }
        uint4* dst = (uint4*)(g_hw_h + grow * HC + cbase);
        const uint4* src = (const uint4*)outv;
        dst[0] = src[0]; dst[1] = src[1]; dst[2] = src[2]; dst[3] = src[3];
        g_as[grow * 2 + hf] = ps;
        g_ad[grow * 2 + hf] = pd;
    }
}

// ---------------- aggregation: one warp per destination node ----------------
__global__ __launch_bounds__(256) void aggregate_kernel(const float* __restrict__ bias)
{
    int wid  = (blockIdx.x * blockDim.x + threadIdx.x) >> 5;
    int lane = threadIdx.x & 31;
    if (wid >= Nn) return;
    int d  = wid;
    int lo = d * BCAP;
    int hi = lo + g_cnt[d];

    int e    = lane >> 2;        // 0..7: edge within group of 8
    int r    = lane & 3;         // channel quarter
    int c    = r * 16;           // channel base
    int head = r >> 1;

    float adh = g_ad[d * 2 + head];

    unsigned long long acc[8];
    #pragma unroll
    for (int i = 0; i < 8; i++) acc[i] = 0ull;
    float wsum = 0.f;

    for (int base = lo; base < hi; base += 8) {
        int k = base + e;
        if (k < hi) {
            int s = g_esrc[k];
            float ev = leaky(g_as[s * 2 + head] + adh);
            float w = __expf(ev);
            unsigned long long w2;
            asm("mov.b64 %0, {%1,%2};" : "=l"(w2) : "f"(w), "f"(w));

            float v[8];
            const __half* hp = g_hw_h + s * HC + c;
            asm("ld.global.nc.v8.f32 {%0,%1,%2,%3,%4,%5,%6,%7}, [%8];"
                : "=f"(v[0]), "=f"(v[1]), "=f"(v[2]), "=f"(v[3]),
                  "=f"(v[4]), "=f"(v[5]), "=f"(v[6]), "=f"(v[7])
                : "l"(hp));

            #pragma unroll
            for (int i = 0; i < 8; i++) {
                unsigned u = __float_as_uint(v[i]);
                float2 f = __half22float2(*(const __half2*)&u);
                unsigned long long fv;
                asm("mov.b64 %0, {%1,%2};" : "=l"(fv) : "f"(f.x), "f"(f.y));
                asm("fma.rn.f32x2 %0, %1, %2, %0;" : "+l"(acc[i]) : "l"(fv), "l"(w2));
            }
            wsum += w;
        }
    }

    float a[16];
    #pragma unroll
    for (int i = 0; i < 8; i++)
        asm("mov.b64 {%0,%1}, %2;" : "=f"(a[2 * i]), "=f"(a[2 * i + 1]) : "l"(acc[i]));

    #pragma unroll
    for (int off = 4; off <= 16; off <<= 1) {
        #pragma unroll
        for (int i = 0; i < 16; i++)
            a[i] += __shfl_xor_sync(0xFFFFFFFFu, a[i], off);
        wsum += __shfl_xor_sync(0xFFFFFFFFu, wsum, off);
    }

    float inv = 1.f / (wsum + 1e-16f);
    int sub = (lane >> 2) * 2;
    int ch  = c + sub;
    float2 bv = *(const float2*)(bias + ch);
    float t0 = fmaf(a[sub],     inv, bv.x);
    float t1 = fmaf(a[sub + 1], inv, bv.y);
    t0 = (t0 > 0.f) ? t0 : (__expf(t0) - 1.f);
    t1 = (t1 > 0.f) ? t1 : (__expf(t1) - 1.f);
    *(__half2*)(g_feat_h + d * HC + ch) = __floats2half2_rn(t0, t1);
}

// ---------------- pooling ----------------
__device__ int lbound32(const int* arr, int n, int key) {
    int lo = 0, hi = n;
    while (lo < hi) {
        int mid = (lo + hi) >> 1;
        if (arr[mid] < key) lo = mid + 1; else hi = mid;
    }
    return lo;
}

__global__ void pool_kernel(const int* __restrict__ batch)
{
    int g = blockIdx.x;
    __shared__ int s_lo, s_hi;
    if (threadIdx.x == 0) {
        s_lo = lbound32(batch, Nn, g);
        s_hi = lbound32(batch, Nn, g + 1);
    }
    __syncthreads();
    int lo = s_lo, hi = s_hi;
    int lane = threadIdx.x & 63;
    int sub  = threadIdx.x >> 6;
    float acc = 0.f;
    for (int n = lo + sub; n < hi; n += 4)
        acc += __half2float(g_feat_h[n * HC + lane]);
    __shared__ float red[4][64];
    red[sub][lane] = acc;
    __syncthreads();
    if (sub == 0) {
        float v = red[0][lane] + red[1][lane] + red[2][lane] + red[3][lane];
        float cnt = (float)(hi - lo);
        v /= fmaxf(cnt, 1.0f);
        g_pooled[g * HC + lane] = v;
    }
}

// ---------------- MLP head ----------------
__global__ void mlp_kernel(const float* __restrict__ w1, const float* __restrict__ b1,
                           const float* __restrict__ w2, const float* __restrict__ b2,
                           float* __restrict__ out)
{
    __shared__ float sw1[Cc * HC];
    __shared__ float sw2[2 * Cc];
    int t = threadIdx.x;
    for (int i = t; i < Cc * HC; i += 64) sw1[i] = w1[i];
    if (t < 2 * Cc) sw2[t] = w2[t];
    __syncthreads();
    if (t >= Gg) return;
    float p[HC];
    #pragma unroll
    for (int i = 0; i < HC; i++) p[i] = g_pooled[t * HC + i];
    float o0 = b2[0], o1 = b2[1];
    #pragma unroll 4
    for (int jj = 0; jj < Cc; jj++) {
        float z = b1[jj];
        #pragma unroll
        for (int i = 0; i < HC; i++) z = fmaf(p[i], sw1[jj * HC + i], z);
        z = fmaxf(z, 0.f);
        o0 = fmaf(z, sw2[jj], o0);
        o1 = fmaf(z, sw2[Cc + jj], o1);
    }
    out[t * 2]     = o0;
    out[t * 2 + 1] = o1;
}

// ---------------- launch ----------------
extern "C" void kernel_launch(void* const* d_in, const int* in_sizes, int n_in,
                              void* d_out, int out_size)
{
    const float* x      = (const float*)d_in[0];
    const int*   ei     = (const int*)d_in[1];
    const int*   batch  = (const int*)d_in[2];
    const float* W[3]     = { (const float*)d_in[3],  (const float*)d_in[7],  (const float*)d_in[11] };
    const float* a_src[3] = { (const float*)d_in[4],  (const float*)d_in[8],  (const float*)d_in[12] };
    const float* a_dst[3] = { (const float*)d_in[5],  (const float*)d_in[9],  (const float*)d_in[13] };
    const float* b[3]     = { (const float*)d_in[6],  (const float*)d_in[10], (const float*)d_in[14] };
    const float* mlp_w1 = (const float*)d_in[15];
    const float* mlp_b1 = (const float*)d_in[16];
    const float* mlp_w2 = (const float*)d_in[17];
    const float* mlp_b2 = (const float*)d_in[18];
    float* out = (float*)d_out;

    wsplit_kernel<<<64, 256>>>(W[0], W[1], W[2]);
    zero_cnt_kernel<<<(Nn + 255) / 256, 256>>>();
    scatter_kernel<<<(EP / 8 + 255) / 256, 256>>>(ei);

    const int gemm_grid = (Nn + 127) / 128;
    const int woff[3] = { 0, F_IN * HC, F_IN * HC + HC * HC };
    for (int l = 0; l < 3; l++) {
        if (l == 0) gemm_wmma_kernel<F_IN><<<gemm_grid, 256>>>(x, woff[l], a_src[l], a_dst[l]);
        else        gemm_wmma_kernel<HC>  <<<gemm_grid, 256>>>(x, woff[l], a_src[l], a_dst[l]);
        aggregate_kernel<<<(Nn * 32 + 255) / 256, 256>>>(b[l]);
    }

    pool_kernel<<<Gg, 256>>>(batch);
    mlp_kernel<<<1, 64>>>(mlp_w1, mlp_b1, mlp_w2, mlp_b2, out);
}

// round 15
// speedup vs baseline: 1.2563x; 1.0400x over previous
#include <cuda_runtime.h>
#include <cuda_fp16.h>
#include <mma.h>
#include <math.h>

using namespace nvcuda;

#define Nn      100000
#define F_IN    128
#define Hh      2
#define Cc      32
#define HC      64
#define Ee      3200000
#define Gg      64
#define EP      (Ee + Nn)       // 3,300,000 (divisible by 8)
#define NEG_SLOPE 0.2f
#define BCAP    96              // bucket capacity (Poisson(33): P(>=95) ~ 0)

#define GEMM_GRID  ((Nn + 127) / 128)          // 782
#define SCAT_GRID  ((EP / 8 + 255) / 256)      // 1612

// ---------------- device scratch (static, no allocation) ----------------
__device__ __half  g_hw_h[Nn * HC];    // h = feat @ W^T (fp16, per layer)
__device__ __half  g_feat_h[Nn * HC];  // layer output after bias+elu (fp16)
__device__ float   g_as[Nn * Hh];
__device__ float   g_ad[Nn * Hh];
__device__ int     g_cnt[Nn];
__device__ int     g_esrc[Nn * BCAP];  // bucketed src lists
__device__ float   g_pooled[Gg * HC];
__device__ __half  g_Wh[F_IN * HC + 2 * HC * HC];   // W hi parts, layers packed
__device__ __half  g_Wl[F_IN * HC + 2 * HC * HC];   // W lo (residual) parts

__device__ __forceinline__ float leaky(float x) { return fmaxf(x, NEG_SLOPE * x); }

// ---------------- prep: W hi/lo split + zero counts (one launch) ----------------
__global__ void prep_kernel(const float* __restrict__ W0,
                            const float* __restrict__ W1,
                            const float* __restrict__ W2)
{
    int i = blockIdx.x * 256 + threadIdx.x;
    if (i < 16384) {
        const float* src; int off;
        if (i < 8192)       { src = W0; off = 0; }
        else if (i < 12288) { src = W1; off = 8192; }
        else                { src = W2; off = 12288; }
        float f = src[i - off];
        __half h = __float2half_rn(f);
        g_Wh[i] = h;
        g_Wl[i] = __float2half_rn(f - __half2float(h));
    }
    if (i < Nn) g_cnt[i] = 0;
}

// ---------------- scatter body (8 edges per thread) ----------------
__device__ __forceinline__ void scatter_body(int blk, const int* __restrict__ ei)
{
    int e8 = (blk * 256 + (int)threadIdx.x) * 8;
    if (e8 >= EP) return;
    if (e8 < Ee) {
        int4 s0 = *(const int4*)(ei + e8);
        int4 s1 = *(const int4*)(ei + e8 + 4);
        int4 d0 = *(const int4*)(ei + Ee + e8);
        int4 d1 = *(const int4*)(ei + Ee + e8 + 4);
        int p0 = atomicAdd(&g_cnt[d0.x], 1);
        int p1 = atomicAdd(&g_cnt[d0.y], 1);
        int p2 = atomicAdd(&g_cnt[d0.z], 1);
        int p3 = atomicAdd(&g_cnt[d0.w], 1);
        int p4 = atomicAdd(&g_cnt[d1.x], 1);
        int p5 = atomicAdd(&g_cnt[d1.y], 1);
        int p6 = atomicAdd(&g_cnt[d1.z], 1);
        int p7 = atomicAdd(&g_cnt[d1.w], 1);
        g_esrc[d0.x * BCAP + p0] = s0.x;
        g_esrc[d0.y * BCAP + p1] = s0.y;
        g_esrc[d0.z * BCAP + p2] = s0.z;
        g_esrc[d0.w * BCAP + p3] = s0.w;
        g_esrc[d1.x * BCAP + p4] = s1.x;
        g_esrc[d1.y * BCAP + p5] = s1.y;
        g_esrc[d1.z * BCAP + p6] = s1.z;
        g_esrc[d1.w * BCAP + p7] = s1.w;
    } else {
        int n = e8 - Ee;
        #pragma unroll
        for (int i = 0; i < 8; i++) {
            int pos = atomicAdd(&g_cnt[n + i], 1);
            g_esrc[(n + i) * BCAP + pos] = n + i;
        }
    }
}

// ---------------- GEMM body (WMMA, W split hi+lo) + fused alpha ----------------
#define LDC 68
#define LDH 72

template<int K>
__device__ __forceinline__ void gemm_body(
    int blk, const float* __restrict__ A_in, int woff,
    const float* __restrict__ a_src, const float* __restrict__ a_dst,
    char* smem)
{
    constexpr int O_BH = 128 * LDH;
    constexpr int O_BL = O_BH + 64 * LDH;

    __half* sH = (__half*)smem;
    float*  sC = (float*)smem;

    int tid = threadIdx.x;
    int wid = tid >> 5;
    int row0 = blk * 128;

    int r  = tid >> 1;
    int hf = tid & 1;
    int cbase = hf * 32;

    wmma::fragment<wmma::accumulator, 16, 16, 16, float> acc[4];
    #pragma unroll
    for (int n = 0; n < 4; n++) wmma::fill_fragment(acc[n], 0.f);

    #pragma unroll
    for (int k0 = 0; k0 < K; k0 += 64) {
        // ---- stage A ----
        {
            int grow = row0 + r;
            int ks = hf * 32;
            if (K == F_IN) {
                __half2 tmp[16];
                if (grow < Nn) {
                    #pragma unroll
                    for (int i = 0; i < 8; i++) {
                        float4 v = *(const float4*)(A_in + grow * K + k0 + ks + i * 4);
                        tmp[2*i]   = __floats2half2_rn(v.x, v.y);
                        tmp[2*i+1] = __floats2half2_rn(v.z, v.w);
                    }
                } else {
                    #pragma unroll
                    for (int i = 0; i < 16; i++) tmp[i] = __floats2half2_rn(0.f, 0.f);
                }
                uint4* dst = (uint4*)(sH + r * LDH + ks);
                const uint4* sp = (const uint4*)tmp;
                dst[0] = sp[0]; dst[1] = sp[1]; dst[2] = sp[2]; dst[3] = sp[3];
            } else {
                uint4 t0, t1, t2, t3;
                if (grow < Nn) {
                    const uint4* src = (const uint4*)(g_feat_h + grow * HC + k0 + ks);
                    t0 = src[0]; t1 = src[1]; t2 = src[2]; t3 = src[3];
                } else {
                    t0 = t1 = t2 = t3 = make_uint4(0, 0, 0, 0);
                }
                uint4* dst = (uint4*)(sH + r * LDH + ks);
                dst[0] = t0; dst[1] = t1; dst[2] = t2; dst[3] = t3;
            }
        }
        // ---- stage B (precomputed hi/lo, pure copies) ----
        {
            int n  = tid >> 2;
            int ks = (tid & 3) * 16;
            const __half* wh = g_Wh + woff + n * K + k0 + ks;
            const __half* wl = g_Wl + woff + n * K + k0 + ks;
            *(uint4*)(sH + O_BH + n * LDH + ks)     = *(const uint4*)(wh);
            *(uint4*)(sH + O_BH + n * LDH + ks + 8) = *(const uint4*)(wh + 8);
            *(uint4*)(sH + O_BL + n * LDH + ks)     = *(const uint4*)(wl);
            *(uint4*)(sH + O_BL + n * LDH + ks + 8) = *(const uint4*)(wl + 8);
        }
        __syncthreads();

        #pragma unroll
        for (int kk = 0; kk < 64; kk += 16) {
            wmma::fragment<wmma::matrix_a, 16, 16, 16, __half, wmma::row_major> a_h;
            wmma::load_matrix_sync(a_h, sH + (wid * 16) * LDH + kk, LDH);
            #pragma unroll
            for (int n = 0; n < 4; n++) {
                wmma::fragment<wmma::matrix_b, 16, 16, 16, __half, wmma::col_major> b_h, b_l;
                wmma::load_matrix_sync(b_h, sH + O_BH + (n * 16) * LDH + kk, LDH);
                wmma::load_matrix_sync(b_l, sH + O_BL + (n * 16) * LDH + kk, LDH);
                wmma::mma_sync(acc[n], a_h, b_h, acc[n]);
                wmma::mma_sync(acc[n], a_h, b_l, acc[n]);
            }
        }
        __syncthreads();
    }

    #pragma unroll
    for (int n = 0; n < 4; n++)
        wmma::store_matrix_sync(sC + (wid * 16) * LDC + n * 16, acc[n], LDC, wmma::mem_row_major);
    __syncthreads();

    int grow = row0 + r;
    if (grow < Nn) {
        const float* cp = sC + r * LDC + cbase;
        float ps = 0.f, pd = 0.f;
        __half2 outv[16];
        #pragma unroll
        for (int i = 0; i < 16; i++) {
            float2 v   = *(const float2*)(cp + 2 * i);
            float2 sa2 = *(const float2*)(a_src + cbase + 2 * i);
            float2 da2 = *(const float2*)(a_dst + cbase + 2 * i);
            ps += v.x * sa2.x + v.y * sa2.y;
            pd += v.x * da2.x + v.y * da2.y;
            outv[i] = __floats2half2_rn(v.x, v.y);
        }
        uint4* dst = (uint4*)(g_hw_h + grow * HC + cbase);
        const uint4* src = (const uint4*)outv;
        dst[0] = src[0]; dst[1] = src[1]; dst[2] = src[2]; dst[3] = src[3];
        g_as[grow * 2 + hf] = ps;
        g_ad[grow * 2 + hf] = pd;
    }
}

constexpr int STAGE_B = (128 * LDH + 2 * 64 * LDH) * 2;   // 36864B
constexpr int C_B     = 128 * LDC * 4;                     // 34816B
constexpr int SMEM_B  = (STAGE_B > C_B) ? STAGE_B : C_B;

// ---------------- fused: layer-0 GEMM + edge scatter (independent work) ----------------
__global__ __launch_bounds__(256, 4) void gemm0_scatter_kernel(
    const float* __restrict__ A_in, const float* __restrict__ a_src,
    const float* __restrict__ a_dst, const int* __restrict__ ei)
{
    __shared__ __align__(128) char smem[SMEM_B];
    if (blockIdx.x < GEMM_GRID) {
        gemm_body<F_IN>(blockIdx.x, A_in, 0, a_src, a_dst, smem);
    } else {
        scatter_body(blockIdx.x - GEMM_GRID, ei);
    }
}

// ---------------- plain GEMM kernel for layers 1/2 ----------------
__global__ __launch_bounds__(256, 4) void gemm_kernel64(
    int woff, const float* __restrict__ a_src, const float* __restrict__ a_dst)
{
    __shared__ __align__(128) char smem[SMEM_B];
    gemm_body<HC>(blockIdx.x, nullptr, woff, a_src, a_dst, smem);
}

// ---------------- aggregation: one warp per destination node ----------------
__global__ __launch_bounds__(256) void aggregate_kernel(const float* __restrict__ bias)
{
    int wid  = (blockIdx.x * blockDim.x + threadIdx.x) >> 5;
    int lane = threadIdx.x & 31;
    if (wid >= Nn) return;
    int d  = wid;
    int lo = d * BCAP;
    int hi = lo + g_cnt[d];

    int e    = lane >> 2;
    int r    = lane & 3;
    int c    = r * 16;
    int head = r >> 1;

    float adh = g_ad[d * 2 + head];

    unsigned long long acc[8];
    #pragma unroll
    for (int i = 0; i < 8; i++) acc[i] = 0ull;
    float wsum = 0.f;

    for (int base = lo; base < hi; base += 8) {
        int k = base + e;
        if (k < hi) {
            int s = g_esrc[k];
            float ev = leaky(g_as[s * 2 + head] + adh);
            float w = __expf(ev);
            unsigned long long w2;
            asm("mov.b64 %0, {%1,%2};" : "=l"(w2) : "f"(w), "f"(w));

            float v[8];
            const __half* hp = g_hw_h + s * HC + c;
            asm("ld.global.nc.v8.f32 {%0,%1,%2,%3,%4,%5,%6,%7}, [%8];"
                : "=f"(v[0]), "=f"(v[1]), "=f"(v[2]), "=f"(v[3]),
                  "=f"(v[4]), "=f"(v[5]), "=f"(v[6]), "=f"(v[7])
                : "l"(hp));

            #pragma unroll
            for (int i = 0; i < 8; i++) {
                unsigned u = __float_as_uint(v[i]);
                float2 f = __half22float2(*(const __half2*)&u);
                unsigned long long fv;
                asm("mov.b64 %0, {%1,%2};" : "=l"(fv) : "f"(f.x), "f"(f.y));
                asm("fma.rn.f32x2 %0, %1, %2, %0;" : "+l"(acc[i]) : "l"(fv), "l"(w2));
            }
            wsum += w;
        }
    }

    float a[16];
    #pragma unroll
    for (int i = 0; i < 8; i++)
        asm("mov.b64 {%0,%1}, %2;" : "=f"(a[2 * i]), "=f"(a[2 * i + 1]) : "l"(acc[i]));

    #pragma unroll
    for (int off = 4; off <= 16; off <<= 1) {
        #pragma unroll
        for (int i = 0; i < 16; i++)
            a[i] += __shfl_xor_sync(0xFFFFFFFFu, a[i], off);
        wsum += __shfl_xor_sync(0xFFFFFFFFu, wsum, off);
    }

    float inv = 1.f / (wsum + 1e-16f);
    int sub = (lane >> 2) * 2;
    int ch  = c + sub;
    float2 bv = *(const float2*)(bias + ch);
    float t0 = fmaf(a[sub],     inv, bv.x);
    float t1 = fmaf(a[sub + 1], inv, bv.y);
    t0 = (t0 > 0.f) ? t0 : (__expf(t0) - 1.f);
    t1 = (t1 > 0.f) ? t1 : (__expf(t1) - 1.f);
    *(__half2*)(g_feat_h + d * HC + ch) = __floats2half2_rn(t0, t1);
}

// ---------------- pooling ----------------
__device__ int lbound32(const int* arr, int n, int key) {
    int lo = 0, hi = n;
    while (lo < hi) {
        int mid = (lo + hi) >> 1;
        if (arr[mid] < key) lo = mid + 1; else hi = mid;
    }
    return lo;
}

__global__ void pool_kernel(const int* __restrict__ batch)
{
    int g = blockIdx.x;
    __shared__ int s_lo, s_hi;
    if (threadIdx.x == 0) {
        s_lo = lbound32(batch, Nn, g);
        s_hi = lbound32(batch, Nn, g + 1);
    }
    __syncthreads();
    int lo = s_lo, hi = s_hi;
    int lane = threadIdx.x & 63;
    int sub  = threadIdx.x >> 6;
    float acc = 0.f;
    for (int n = lo + sub; n < hi; n += 4)
        acc += __half2float(g_feat_h[n * HC + lane]);
    __shared__ float red[4][64];
    red[sub][lane] = acc;
    __syncthreads();
    if (sub == 0) {
        float v = red[0][lane] + red[1][lane] + red[2][lane] + red[3][lane];
        float cnt = (float)(hi - lo);
        v /= fmaxf(cnt, 1.0f);
        g_pooled[g * HC + lane] = v;
    }
}

// ---------------- MLP head ----------------
__global__ void mlp_kernel(const float* __restrict__ w1, const float* __restrict__ b1,
                           const float* __restrict__ w2, const float* __restrict__ b2,
                           float* __restrict__ out)
{
    __shared__ float sw1[Cc * HC];
    __shared__ float sw2[2 * Cc];
    int t = threadIdx.x;
    for (int i = t; i < Cc * HC; i += 64) sw1[i] = w1[i];
    if (t < 2 * Cc) sw2[t] = w2[t];
    __syncthreads();
    if (t >= Gg) return;
    float p[HC];
    #pragma unroll
    for (int i = 0; i < HC; i++) p[i] = g_pooled[t * HC + i];
    float o0 = b2[0], o1 = b2[1];
    #pragma unroll 4
    for (int jj = 0; jj < Cc; jj++) {
        float z = b1[jj];
        #pragma unroll
        for (int i = 0; i < HC; i++) z = fmaf(p[i], sw1[jj * HC + i], z);
        z = fmaxf(z, 0.f);
        o0 = fmaf(z, sw2[jj], o0);
        o1 = fmaf(z, sw2[Cc + jj], o1);
    }
    out[t * 2]     = o0;
    out[t * 2 + 1] = o1;
}

// ---------------- launch ----------------
extern "C" void kernel_launch(void* const* d_in, const int* in_sizes, int n_in,
                              void* d_out, int out_size)
{
    const float* x      = (const float*)d_in[0];
    const int*   ei     = (const int*)d_in[1];
    const int*   batch  = (const int*)d_in[2];
    const float* a_src[3] = { (const float*)d_in[4],  (const float*)d_in[8],  (const float*)d_in[12] };
    const float* a_dst[3] = { (const float*)d_in[5],  (const float*)d_in[9],  (const float*)d_in[13] };
    const float* b[3]     = { (const float*)d_in[6],  (const float*)d_in[10], (const float*)d_in[14] };
    const float* mlp_w1 = (const float*)d_in[15];
    const float* mlp_b1 = (const float*)d_in[16];
    const float* mlp_w2 = (const float*)d_in[17];
    const float* mlp_b2 = (const float*)d_in[18];
    float* out = (float*)d_out;

    // prep: W hi/lo split + zero counts
    prep_kernel<<<(Nn + 255) / 256, 256>>>((const float*)d_in[3], (const float*)d_in[7],
                                           (const float*)d_in[11]);

    // fused: layer-0 GEMM (independent of adjacency) + edge scatter
    gemm0_scatter_kernel<<<GEMM_GRID + SCAT_GRID, 256>>>(x, a_src[0], a_dst[0], ei);
    aggregate_kernel<<<(Nn * 32 + 255) / 256, 256>>>(b[0]);

    const int woff[3] = { 0, F_IN * HC, F_IN * HC + HC * HC };
    for (int l = 1; l < 3; l++) {
        gemm_kernel64<<<GEMM_GRID, 256>>>(woff[l], a_src[l], a_dst[l]);
        aggregate_kernel<<<(Nn * 32 + 255) / 256, 256>>>(b[l]);
    }

    pool_kernel<<<Gg, 256>>>(batch);
    mlp_kernel<<<1, 64>>>(mlp_w1, mlp_b1, mlp_w2, mlp_b2, out);
}

// round 16
// speedup vs baseline: 1.2624x; 1.0049x over previous
#include <cuda_runtime.h>
#include <cuda_fp16.h>
#include <mma.h>
#include <math.h>

using namespace nvcuda;

#define Nn      100000
#define F_IN    128
#define Hh      2
#define Cc      32
#define HC      64
#define Ee      3200000
#define Gg      64
#define EP      (Ee + Nn)       // 3,300,000 (divisible by 8)
#define NEG_SLOPE 0.2f
#define BCAP    96              // bucket capacity (Poisson(33): P(>=95) ~ 0)

#define GEMM_GRID  ((Nn + 127) / 128)          // 782
#define SCAT_GRID  ((EP / 8 + 255) / 256)      // 1612

// ---------------- device scratch (static, no allocation) ----------------
__device__ __half  g_hw_h[Nn * HC];    // h = feat @ W^T (fp16, per layer)
__device__ __half  g_feat_h[Nn * HC];  // layer output after bias+elu (fp16)
__device__ float   g_as[Nn * Hh];
__device__ float   g_ad[Nn * Hh];
__device__ int     g_cnt[Nn];
__device__ int     g_esrc[Nn * BCAP];  // bucketed src lists
__device__ float   g_pooled[Gg * HC];
__device__ __half  g_Wh[F_IN * HC + 2 * HC * HC];   // W hi parts, layers packed
__device__ __half  g_Wl[F_IN * HC + 2 * HC * HC];   // W lo (residual) parts

__device__ __forceinline__ float leaky(float x) { return fmaxf(x, NEG_SLOPE * x); }

// ---------------- prep: W hi/lo split + zero counts (one launch) ----------------
__global__ void prep_kernel(const float* __restrict__ W0,
                            const float* __restrict__ W1,
                            const float* __restrict__ W2)
{
    int i = blockIdx.x * 256 + threadIdx.x;
    if (i < 16384) {
        const float* src; int off;
        if (i < 8192)       { src = W0; off = 0; }
        else if (i < 12288) { src = W1; off = 8192; }
        else                { src = W2; off = 12288; }
        float f = src[i - off];
        __half h = __float2half_rn(f);
        g_Wh[i] = h;
        g_Wl[i] = __float2half_rn(f - __half2float(h));
    }
    if (i < Nn) g_cnt[i] = 0;
}

// ---------------- scatter body (8 edges per thread) ----------------
__device__ __forceinline__ void scatter_body(int blk, const int* __restrict__ ei)
{
    int e8 = (blk * 256 + (int)threadIdx.x) * 8;
    if (e8 >= EP) return;
    if (e8 < Ee) {
        int4 s0 = *(const int4*)(ei + e8);
        int4 s1 = *(const int4*)(ei + e8 + 4);
        int4 d0 = *(const int4*)(ei + Ee + e8);
        int4 d1 = *(const int4*)(ei + Ee + e8 + 4);
        int p0 = atomicAdd(&g_cnt[d0.x], 1);
        int p1 = atomicAdd(&g_cnt[d0.y], 1);
        int p2 = atomicAdd(&g_cnt[d0.z], 1);
        int p3 = atomicAdd(&g_cnt[d0.w], 1);
        int p4 = atomicAdd(&g_cnt[d1.x], 1);
        int p5 = atomicAdd(&g_cnt[d1.y], 1);
        int p6 = atomicAdd(&g_cnt[d1.z], 1);
        int p7 = atomicAdd(&g_cnt[d1.w], 1);
        g_esrc[d0.x * BCAP + p0] = s0.x;
        g_esrc[d0.y * BCAP + p1] = s0.y;
        g_esrc[d0.z * BCAP + p2] = s0.z;
        g_esrc[d0.w * BCAP + p3] = s0.w;
        g_esrc[d1.x * BCAP + p4] = s1.x;
        g_esrc[d1.y * BCAP + p5] = s1.y;
        g_esrc[d1.z * BCAP + p6] = s1.z;
        g_esrc[d1.w * BCAP + p7] = s1.w;
    } else {
        int n = e8 - Ee;
        #pragma unroll
        for (int i = 0; i < 8; i++) {
            int pos = atomicAdd(&g_cnt[n + i], 1);
            g_esrc[(n + i) * BCAP + pos] = n + i;
        }
    }
}

// ---------------- GEMM body (WMMA, W split hi+lo) + fused alpha ----------------
#define LDC 68
#define LDH 72

template<int K>
__device__ __forceinline__ void gemm_body(
    int blk, const float* __restrict__ A_in, int woff,
    const float* __restrict__ a_src, const float* __restrict__ a_dst,
    char* smem)
{
    constexpr int O_BH = 128 * LDH;
    constexpr int O_BL = O_BH + 64 * LDH;

    __half* sH = (__half*)smem;
    float*  sC = (float*)smem;

    int tid = threadIdx.x;
    int wid = tid >> 5;
    int row0 = blk * 128;

    int r  = tid >> 1;
    int hf = tid & 1;
    int cbase = hf * 32;

    wmma::fragment<wmma::accumulator, 16, 16, 16, float> acc[4];
    #pragma unroll
    for (int n = 0; n < 4; n++) wmma::fill_fragment(acc[n], 0.f);

    #pragma unroll
    for (int k0 = 0; k0 < K; k0 += 64) {
        // ---- stage A ----
        {
            int grow = row0 + r;
            int ks = hf * 32;
            if (K == F_IN) {
                __half2 tmp[16];
                if (grow < Nn) {
                    #pragma unroll
                    for (int i = 0; i < 8; i++) {
                        float4 v = *(const float4*)(A_in + grow * K + k0 + ks + i * 4);
                        tmp[2*i]   = __floats2half2_rn(v.x, v.y);
                        tmp[2*i+1] = __floats2half2_rn(v.z, v.w);
                    }
                } else {
                    #pragma unroll
                    for (int i = 0; i < 16; i++) tmp[i] = __floats2half2_rn(0.f, 0.f);
                }
                uint4* dst = (uint4*)(sH + r * LDH + ks);
                const uint4* sp = (const uint4*)tmp;
                dst[0] = sp[0]; dst[1] = sp[1]; dst[2] = sp[2]; dst[3] = sp[3];
            } else {
                uint4 t0, t1, t2, t3;
                if (grow < Nn) {
                    const uint4* src = (const uint4*)(g_feat_h + grow * HC + k0 + ks);
                    t0 = src[0]; t1 = src[1]; t2 = src[2]; t3 = src[3];
                } else {
                    t0 = t1 = t2 = t3 = make_uint4(0, 0, 0, 0);
                }
                uint4* dst = (uint4*)(sH + r * LDH + ks);
                dst[0] = t0; dst[1] = t1; dst[2] = t2; dst[3] = t3;
            }
        }
        // ---- stage B (precomputed hi/lo, pure copies) ----
        {
            int n  = tid >> 2;
            int ks = (tid & 3) * 16;
            const __half* wh = g_Wh + woff + n * K + k0 + ks;
            const __half* wl = g_Wl + woff + n * K + k0 + ks;
            *(uint4*)(sH + O_BH + n * LDH + ks)     = *(const uint4*)(wh);
            *(uint4*)(sH + O_BH + n * LDH + ks + 8) = *(const uint4*)(wh + 8);
            *(uint4*)(sH + O_BL + n * LDH + ks)     = *(const uint4*)(wl);
            *(uint4*)(sH + O_BL + n * LDH + ks + 8) = *(const uint4*)(wl + 8);
        }
        __syncthreads();

        #pragma unroll
        for (int kk = 0; kk < 64; kk += 16) {
            wmma::fragment<wmma::matrix_a, 16, 16, 16, __half, wmma::row_major> a_h;
            wmma::load_matrix_sync(a_h, sH + (wid * 16) * LDH + kk, LDH);
            #pragma unroll
            for (int n = 0; n < 4; n++) {
                wmma::fragment<wmma::matrix_b, 16, 16, 16, __half, wmma::col_major> b_h, b_l;
                wmma::load_matrix_sync(b_h, sH + O_BH + (n * 16) * LDH + kk, LDH);
                wmma::load_matrix_sync(b_l, sH + O_BL + (n * 16) * LDH + kk, LDH);
                wmma::mma_sync(acc[n], a_h, b_h, acc[n]);
                wmma::mma_sync(acc[n], a_h, b_l, acc[n]);
            }
        }
        __syncthreads();
    }

    #pragma unroll
    for (int n = 0; n < 4; n++)
        wmma::store_matrix_sync(sC + (wid * 16) * LDC + n * 16, acc[n], LDC, wmma::mem_row_major);
    __syncthreads();

    int grow = row0 + r;
    if (grow < Nn) {
        const float* cp = sC + r * LDC + cbase;
        float ps = 0.f, pd = 0.f;
        __half2 outv[16];
        #pragma unroll
        for (int i = 0; i < 16; i++) {
            float2 v   = *(const float2*)(cp + 2 * i);
            float2 sa2 = *(const float2*)(a_src + cbase + 2 * i);
            float2 da2 = *(const float2*)(a_dst + cbase + 2 * i);
            ps += v.x * sa2.x + v.y * sa2.y;
            pd += v.x * da2.x + v.y * da2.y;
            outv[i] = __floats2half2_rn(v.x, v.y);
        }
        uint4* dst = (uint4*)(g_hw_h + grow * HC + cbase);
        const uint4* src = (const uint4*)outv;
        dst[0] = src[0]; dst[1] = src[1]; dst[2] = src[2]; dst[3] = src[3];
        g_as[grow * 2 + hf] = ps;
        g_ad[grow * 2 + hf] = pd;
    }
}

constexpr int STAGE_B = (128 * LDH + 2 * 64 * LDH) * 2;   // 36864B
constexpr int C_B     = 128 * LDC * 4;                     // 34816B
constexpr int SMEM_B  = (STAGE_B > C_B) ? STAGE_B : C_B;

// ---------------- fused: layer-0 GEMM + edge scatter (independent work) ----------------
__global__ __launch_bounds__(256, 4) void gemm0_scatter_kernel(
    const float* __restrict__ A_in, const float* __restrict__ a_src,
    const float* __restrict__ a_dst, const int* __restrict__ ei)
{
    __shared__ __align__(128) char smem[SMEM_B];
    if (blockIdx.x < GEMM_GRID) {
        gemm_body<F_IN>(blockIdx.x, A_in, 0, a_src, a_dst, smem);
    } else {
        scatter_body(blockIdx.x - GEMM_GRID, ei);
    }
}

// ---------------- plain GEMM kernel for layers 1/2 ----------------
__global__ __launch_bounds__(256, 4) void gemm_kernel64(
    int woff, const float* __restrict__ a_src, const float* __restrict__ a_dst)
{
    __shared__ __align__(128) char smem[SMEM_B];
    gemm_body<HC>(blockIdx.x, nullptr, woff, a_src, a_dst, smem);
}

// ---------------- aggregation: one warp per destination node ----------------
// 16 edges per loop trip: two independently-guarded 8-edge groups.
// Lane layout per group: e = lane>>2 (edge 0..7), lane&3 -> channel quarter.
__device__ __forceinline__ void agg_group(int k, int head, float adh, int c,
                                          unsigned long long* acc, float& wsum)
{
    int s = g_esrc[k];
    float ev = leaky(g_as[s * 2 + head] + adh);
    float w = __expf(ev);
    unsigned long long w2;
    asm("mov.b64 %0, {%1,%2};" : "=l"(w2) : "f"(w), "f"(w));

    float v[8];
    const __half* hp = g_hw_h + s * HC + c;
    asm("ld.global.nc.v8.f32 {%0,%1,%2,%3,%4,%5,%6,%7}, [%8];"
        : "=f"(v[0]), "=f"(v[1]), "=f"(v[2]), "=f"(v[3]),
          "=f"(v[4]), "=f"(v[5]), "=f"(v[6]), "=f"(v[7])
        : "l"(hp));

    #pragma unroll
    for (int i = 0; i < 8; i++) {
        unsigned u = __float_as_uint(v[i]);
        float2 f = __half22float2(*(const __half2*)&u);
        unsigned long long fv;
        asm("mov.b64 %0, {%1,%2};" : "=l"(fv) : "f"(f.x), "f"(f.y));
        asm("fma.rn.f32x2 %0, %1, %2, %0;" : "+l"(acc[i]) : "l"(fv), "l"(w2));
    }
    wsum += w;
}

__global__ __launch_bounds__(256) void aggregate_kernel(const float* __restrict__ bias)
{
    int wid  = (blockIdx.x * blockDim.x + threadIdx.x) >> 5;
    int lane = threadIdx.x & 31;
    if (wid >= Nn) return;
    int d  = wid;
    int lo = d * BCAP;
    int hi = lo + g_cnt[d];

    int e    = lane >> 2;        // edge within group of 8
    int r    = lane & 3;         // channel quarter
    int c    = r * 16;
    int head = r >> 1;

    float adh = g_ad[d * 2 + head];

    unsigned long long acc[8];
    #pragma unroll
    for (int i = 0; i < 8; i++) acc[i] = 0ull;
    float wsum = 0.f;

    for (int base = lo; base < hi; base += 16) {
        int k1 = base + e;
        int k2 = base + 8 + e;
        if (k1 < hi) agg_group(k1, head, adh, c, acc, wsum);
        if (k2 < hi) agg_group(k2, head, adh, c, acc, wsum);
    }

    float a[16];
    #pragma unroll
    for (int i = 0; i < 8; i++)
        asm("mov.b64 {%0,%1}, %2;" : "=f"(a[2 * i]), "=f"(a[2 * i + 1]) : "l"(acc[i]));

    #pragma unroll
    for (int off = 4; off <= 16; off <<= 1) {
        #pragma unroll
        for (int i = 0; i < 16; i++)
            a[i] += __shfl_xor_sync(0xFFFFFFFFu, a[i], off);
        wsum += __shfl_xor_sync(0xFFFFFFFFu, wsum, off);
    }

    float inv = 1.f / (wsum + 1e-16f);
    int sub = (lane >> 2) * 2;
    int ch  = c + sub;
    float2 bv = *(const float2*)(bias + ch);
    float t0 = fmaf(a[sub],     inv, bv.x);
    float t1 = fmaf(a[sub + 1], inv, bv.y);
    t0 = (t0 > 0.f) ? t0 : (__expf(t0) - 1.f);
    t1 = (t1 > 0.f) ? t1 : (__expf(t1) - 1.f);
    *(__half2*)(g_feat_h + d * HC + ch) = __floats2half2_rn(t0, t1);
}

// ---------------- pooling ----------------
__device__ int lbound32(const int* arr, int n, int key) {
    int lo = 0, hi = n;
    while (lo < hi) {
        int mid = (lo + hi) >> 1;
        if (arr[mid] < key) lo = mid + 1; else hi = mid;
    }
    return lo;
}

__global__ void pool_kernel(const int* __restrict__ batch)
{
    int g = blockIdx.x;
    __shared__ int s_lo, s_hi;
    if (threadIdx.x == 0) {
        s_lo = lbound32(batch, Nn, g);
        s_hi = lbound32(batch, Nn, g + 1);
    }
    __syncthreads();
    int lo = s_lo, hi = s_hi;
    int lane = threadIdx.x & 63;
    int sub  = threadIdx.x >> 6;
    float acc = 0.f;
    for (int n = lo + sub; n < hi; n += 4)
        acc += __half2float(g_feat_h[n * HC + lane]);
    __shared__ float red[4][64];
    red[sub][lane] = acc;
    __syncthreads();
    if (sub == 0) {
        float v = red[0][lane] + red[1][lane] + red[2][lane] + red[3][lane];
        float cnt = (float)(hi - lo);
        v /= fmaxf(cnt, 1.0f);
        g_pooled[g * HC + lane] = v;
    }
}

// ---------------- MLP head ----------------
__global__ void mlp_kernel(const float* __restrict__ w1, const float* __restrict__ b1,
                           const float* __restrict__ w2, const float* __restrict__ b2,
                           float* __restrict__ out)
{
    __shared__ float sw1[Cc * HC];
    __shared__ float sw2[2 * Cc];
    int t = threadIdx.x;
    for (int i = t; i < Cc * HC; i += 64) sw1[i] = w1[i];
    if (t < 2 * Cc) sw2[t] = w2[t];
    __syncthreads();
    if (t >= Gg) return;
    float p[HC];
    #pragma unroll
    for (int i = 0; i < HC; i++) p[i] = g_pooled[t * HC + i];
    float o0 = b2[0], o1 = b2[1];
    #pragma unroll 4
    for (int jj = 0; jj < Cc; jj++) {
        float z = b1[jj];
        #pragma unroll
        for (int i = 0; i < HC; i++) z = fmaf(p[i], sw1[jj * HC + i], z);
        z = fmaxf(z, 0.f);
        o0 = fmaf(z, sw2[jj], o0);
        o1 = fmaf(z, sw2[Cc + jj], o1);
    }
    out[t * 2]     = o0;
    out[t * 2 + 1] = o1;
}

// ---------------- launch ----------------
extern "C" void kernel_launch(void* const* d_in, const int* in_sizes, int n_in,
                              void* d_out, int out_size)
{
    const float* x      = (const float*)d_in[0];
    const int*   ei     = (const int*)d_in[1];
    const int*   batch  = (const int*)d_in[2];
    const float* a_src[3] = { (const float*)d_in[4],  (const float*)d_in[8],  (const float*)d_in[12] };
    const float* a_dst[3] = { (const float*)d_in[5],  (const float*)d_in[9],  (const float*)d_in[13] };
    const float* b[3]     = { (const float*)d_in[6],  (const float*)d_in[10], (const float*)d_in[14] };
    const float* mlp_w1 = (const float*)d_in[15];
    const float* mlp_b1 = (const float*)d_in[16];
    const float* mlp_w2 = (const float*)d_in[17];
    const float* mlp_b2 = (const float*)d_in[18];
    float* out = (float*)d_out;

    prep_kernel<<<(Nn + 255) / 256, 256>>>((const float*)d_in[3], (const float*)d_in[7],
                                           (const float*)d_in[11]);

    gemm0_scatter_kernel<<<GEMM_GRID + SCAT_GRID, 256>>>(x, a_src[0], a_dst[0], ei);
    aggregate_kernel<<<(Nn * 32 + 255) / 256, 256>>>(b[0]);

    const int woff[3] = { 0, F_IN * HC, F_IN * HC + HC * HC };
    for (int l = 1; l < 3; l++) {
        gemm_kernel64<<<GEMM_GRID, 256>>>(woff[l], a_src[l], a_dst[l]);
        aggregate_kernel<<<(Nn * 32 + 255) / 256, 256>>>(b[l]);
    }

    pool_kernel<<<Gg, 256>>>(batch);
    mlp_kernel<<<1, 64>>>(mlp_w1, mlp_b1, mlp_w2, mlp_b2, out);
}